// round 7
// baseline (speedup 1.0000x reference)
#include <cuda_runtime.h>
#include <cuda_bf16.h>
#include <math.h>

// Problem shape (fixed by the bench)
#define TT   256
#define BBB  128
#define DD   300
#define HHH  256
#define GGG  1024              // 4*H
#define MROWS (TT*BBB)         // 32768

// ---------------- static device scratch (no runtime allocation) -------------
__device__ float    d_XGF[(size_t)MROWS * GGG];      // gate preacts fwd (reused for ann)
__device__ float    d_XGR[(size_t)MROWS * GGG];      // gate preacts rev
__device__ float    d_H1 [(size_t)MROWS * 2 * HHH];  // layer-1 output
__device__ float    d_H2 [(size_t)MROWS * 2 * HHH];  // layer-2 output
__device__ float    d_Hx [16 * 2 * 256 * 16];        // h exchange: [grp][buf][u][b]
__device__ unsigned d_bar[16];                       // group barriers

// ============================================================================
// SGEMM  C[m][n] = A[m][:] . W[n][:] (+ epilogue)
//   A: [M,K] row-major, W: [N,K] row-major
//   MODE 0: C = acc + b1[n] + b2[n]
//   MODE 1: C = tanh(acc + b1[n])
// Tiles: BM=BN=128, BK=8, 256 threads, 8x8 microtile (split 4+4 for LDS.128).
// Requires M%128==0 and N%128==0 (holds). K arbitrary (guarded).
// ============================================================================
template <int MODE>
__global__ void __launch_bounds__(256, 2)
sgemm_bias(const float* __restrict__ A, const float* __restrict__ W,
           const float* __restrict__ b1, const float* __restrict__ b2,
           float* __restrict__ C, int M, int N, int K)
{
    __shared__ float As[8][128];
    __shared__ float Bs[8][128];

    const int tid  = threadIdx.x;
    const int bm   = blockIdx.y;
    const int bn   = blockIdx.x;
    const int tx   = tid & 15;          // 0..15 -> columns
    const int ty   = tid >> 4;          // 0..15 -> rows
    const int lrow = tid >> 1;          // 0..127 (load row)
    const int lk   = (tid & 1) * 4;     // 0 or 4 (load k offset)

    const float* Arow = A + (size_t)(bm * 128 + lrow) * K;
    const float* Wrow = W + (size_t)(bn * 128 + lrow) * K;

    float acc[8][8];
#pragma unroll
    for (int i = 0; i < 8; ++i)
#pragma unroll
        for (int j = 0; j < 8; ++j) acc[i][j] = 0.0f;

    for (int kt = 0; kt < K; kt += 8) {
        float a4[4], b4[4];
#pragma unroll
        for (int c = 0; c < 4; ++c) {
            int k = kt + lk + c;
            a4[c] = (k < K) ? Arow[k] : 0.0f;
            b4[c] = (k < K) ? Wrow[k] : 0.0f;
        }
        __syncthreads();
#pragma unroll
        for (int c = 0; c < 4; ++c) {
            As[lk + c][lrow] = a4[c];
            Bs[lk + c][lrow] = b4[c];
        }
        __syncthreads();
#pragma unroll
        for (int k = 0; k < 8; ++k) {
            float ar[8], br[8];
            *(float4*)&ar[0] = *(const float4*)&As[k][ty * 4];
            *(float4*)&ar[4] = *(const float4*)&As[k][64 + ty * 4];
            *(float4*)&br[0] = *(const float4*)&Bs[k][tx * 4];
            *(float4*)&br[4] = *(const float4*)&Bs[k][64 + tx * 4];
#pragma unroll
            for (int i = 0; i < 8; ++i)
#pragma unroll
                for (int j = 0; j < 8; ++j)
                    acc[i][j] += ar[i] * br[j];
        }
    }

    // epilogue
#pragma unroll
    for (int i = 0; i < 8; ++i) {
        int m = bm * 128 + ((i < 4) ? (ty * 4 + i) : (64 + ty * 4 + (i - 4)));
#pragma unroll
        for (int jj = 0; jj < 2; ++jj) {
            int n0 = bn * 128 + (jj ? (64 + tx * 4) : (tx * 4));
            float4 v;
            float* vp = &v.x;
#pragma unroll
            for (int c = 0; c < 4; ++c) {
                float val = acc[i][jj * 4 + c];
                int n = n0 + c;
                if (MODE == 0) val += b1[n] + b2[n];
                else           val  = tanhf(val + b1[n]);
                vp[c] = val;
            }
            *(float4*)&C[(size_t)m * N + n0] = v;
        }
    }
}

// ============================================================================
// Barrier reset (run before each recurrence launch)
// ============================================================================
__global__ void reset_bar_kernel() {
    if (threadIdx.x < 16) d_bar[threadIdx.x] = 0u;
}

// ============================================================================
// Persistent bidirectional LSTM layer.
// grid = 128 CTAs: slice = bid&7 (32 hidden units), chunk = (bid>>3)&7 (16 batch),
// dir = bid>>6. 8 CTAs per (dir,chunk) group exchange h through d_Hx (double-
// buffered) with a monotonic atomic-counter barrier. 128 threads/CTA; thread
// (uu = tid&31, bgroup = (tid>>5)*4) computes gates i,f,g,o for hidden unit
// slice*32+uu over 4 batch elements; cell state c lives in registers.
// smem: Wsh[128][260] (this CTA's 128 W_hh rows) + Hs[16][260] + lens[16].
// ============================================================================
#define WS 260
#define LSTM_SMEM ((128 * WS + 16 * WS + 16) * 4)

__global__ void __launch_bounds__(128, 1)
lstm_layer(const float* __restrict__ xgF, const float* __restrict__ xgR,
           const float* __restrict__ whhF, const float* __restrict__ whhR,
           const int* __restrict__ lengths, float* __restrict__ out)
{
    extern __shared__ float sm[];
    float* Wsh  = sm;                    // 128*260
    float* Hs   = sm + 128 * WS;         // 16*260
    int*   lens = (int*)(Hs + 16 * WS);  // 16

    const int tid   = threadIdx.x;
    const int bid   = blockIdx.x;
    const int slice = bid & 7;
    const int chunk = (bid >> 3) & 7;
    const int dir   = bid >> 6;
    const int grp   = dir * 8 + chunk;

    const float* whh = dir ? whhR : whhF;
    const float* xg  = dir ? xgR : xgF;

    if (tid < 16) {
        int l = lengths[chunk * 16 + tid];
        lens[tid] = (l < 1) ? 1 : l;
    }

    // Load this CTA's 128 W_hh rows (i/f/g/o x 32 units) into SMEM, stride 260.
    for (int i = tid; i < 128 * 64; i += 128) {
        int r  = i >> 6;         // 0..127
        int k4 = i & 63;         // 0..63
        int g  = r >> 5;
        int uu = r & 31;
        float4 v = *(const float4*)&whh[(size_t)(g * 256 + slice * 32 + uu) * 256 + k4 * 4];
        float* dst = &Wsh[r * WS + k4 * 4];
        dst[0] = v.x; dst[1] = v.y; dst[2] = v.z; dst[3] = v.w;
    }
    __syncthreads();

    const int uu = tid & 31;
    const int bg = (tid >> 5) << 2;   // 0,4,8,12
    const float* w0 = Wsh + uu * WS;
    const float* w1 = w0 + 32 * WS;
    const float* w2 = w0 + 64 * WS;
    const float* w3 = w0 + 96 * WS;

    float c[4] = {0.f, 0.f, 0.f, 0.f};

    for (int s = 0; s < TT; ++s) {
        // --- bring previous h into SMEM -------------------------------------
        if (s == 0) {
            for (int i = tid; i < 16 * WS; i += 128) Hs[i] = 0.0f;
        } else {
            int buf = s & 1;
            const float* src = d_Hx + ((size_t)(grp * 2 + buf)) * 4096;
            for (int i = tid; i < 4096; i += 128) {
                int u = i >> 4, b = i & 15;
                Hs[b * WS + u] = src[i];
            }
        }
        __syncthreads();

        // --- per-batch time index (reverse-padded mapping; involution) ------
        int t[4];
#pragma unroll
        for (int j = 0; j < 4; ++j) {
            int len = lens[bg + j];
            t[j] = dir ? ((s < len) ? (len - 1 - s) : s) : s;
        }

        // --- gate preactivations from xg ------------------------------------
        float a0[4], a1[4], a2[4], a3[4];
#pragma unroll
        for (int j = 0; j < 4; ++j) {
            size_t row = ((size_t)t[j] * BBB + chunk * 16 + bg + j) * GGG;
            int col = slice * 32 + uu;
            a0[j] = xg[row +   0 + col];
            a1[j] = xg[row + 256 + col];
            a2[j] = xg[row + 512 + col];
            a3[j] = xg[row + 768 + col];
        }

        const float* h0 = Hs + (bg + 0) * WS;
        const float* h1 = Hs + (bg + 1) * WS;
        const float* h2 = Hs + (bg + 2) * WS;
        const float* h3 = Hs + (bg + 3) * WS;

#pragma unroll 4
        for (int k4 = 0; k4 < 64; ++k4) {
            float4 W0 = *(const float4*)(w0 + k4 * 4);
            float4 W1 = *(const float4*)(w1 + k4 * 4);
            float4 W2 = *(const float4*)(w2 + k4 * 4);
            float4 W3 = *(const float4*)(w3 + k4 * 4);
            float4 H0 = *(const float4*)(h0 + k4 * 4);
            float4 H1v = *(const float4*)(h1 + k4 * 4);
            float4 H2v = *(const float4*)(h2 + k4 * 4);
            float4 H3v = *(const float4*)(h3 + k4 * 4);
#define DOT4(acc, Wv, Hv) acc += Wv.x*Hv.x + Wv.y*Hv.y + Wv.z*Hv.z + Wv.w*Hv.w
            DOT4(a0[0], W0, H0); DOT4(a0[1], W0, H1v); DOT4(a0[2], W0, H2v); DOT4(a0[3], W0, H3v);
            DOT4(a1[0], W1, H0); DOT4(a1[1], W1, H1v); DOT4(a1[2], W1, H2v); DOT4(a1[3], W1, H3v);
            DOT4(a2[0], W2, H0); DOT4(a2[1], W2, H1v); DOT4(a2[2], W2, H2v); DOT4(a2[3], W2, H3v);
            DOT4(a3[0], W3, H0); DOT4(a3[1], W3, H1v); DOT4(a3[2], W3, H2v); DOT4(a3[3], W3, H3v);
#undef DOT4
        }

        // --- LSTM cell (torch gate order i,f,g,o) ---------------------------
        float hnew[4];
#pragma unroll
        for (int j = 0; j < 4; ++j) {
            float ig = 1.0f / (1.0f + __expf(-a0[j]));
            float fg = 1.0f / (1.0f + __expf(-a1[j]));
            float gg = tanhf(a2[j]);
            float og = 1.0f / (1.0f + __expf(-a3[j]));
            c[j] = fg * c[j] + ig * gg;
            hnew[j] = og * tanhf(c[j]);
        }

        // --- write layer output + exchange buffer ---------------------------
        int col = dir * 256 + slice * 32 + uu;
#pragma unroll
        for (int j = 0; j < 4; ++j)
            out[((size_t)t[j] * BBB + chunk * 16 + bg + j) * 512 + col] = hnew[j];

        {
            int buf = (s + 1) & 1;
            float* dst = d_Hx + ((size_t)(grp * 2 + buf)) * 4096
                              + (slice * 32 + uu) * 16 + bg;
            dst[0] = hnew[0]; dst[1] = hnew[1]; dst[2] = hnew[2]; dst[3] = hnew[3];
        }
        __syncthreads();

        // --- group barrier (monotonic counter, 8 CTAs) ----------------------
        if (s < TT - 1) {
            if (tid == 0) {
                __threadfence();
                atomicAdd(&d_bar[grp], 1u);
                unsigned target = 8u * (unsigned)(s + 1);
                unsigned spins = 0;
                while (*((volatile unsigned*)&d_bar[grp]) < target) {
                    if (++spins > (1u << 22)) break;   // safety bail, never taken
                }
                __threadfence();
            }
            __syncthreads();
        }
    }
}

// ============================================================================
// Attention: per-batch masked softmax over time + weighted sum.
// ann[m][e] = tanh(h2 . mlp_w + mlp_b) precomputed by sgemm MODE 1.
// grid = B blocks, 256 threads (one thread per time step for the scores).
// ============================================================================
__global__ void __launch_bounds__(256)
attn_kernel(const float* __restrict__ h2, const float* __restrict__ ann,
            const float* __restrict__ ctx, const int* __restrict__ lengths,
            float* __restrict__ outp)
{
    __shared__ float ctxs[512];
    __shared__ float sc[256];
    __shared__ float red[8];

    const int b = blockIdx.x;
    const int tid = threadIdx.x;

    for (int i = tid; i < 512; i += 256) ctxs[i] = ctx[i];
    __syncthreads();

    // score for t = tid
    {
        const float* row = ann + ((size_t)tid * BBB + b) * 512;
        float s = 0.0f;
        for (int e = 0; e < 512; e += 4) {
            float4 v = *(const float4*)(row + e);
            s += v.x * ctxs[e] + v.y * ctxs[e + 1] + v.z * ctxs[e + 2] + v.w * ctxs[e + 3];
        }
        int len = lengths[b]; if (len < 1) len = 1;
        sc[tid] = (tid < len) ? s : -1e9f;
    }
    __syncthreads();

    // block softmax over 256 values
    float v = sc[tid];
    for (int o = 16; o; o >>= 1) v = fmaxf(v, __shfl_xor_sync(0xffffffffu, v, o));
    if ((tid & 31) == 0) red[tid >> 5] = v;
    __syncthreads();
    float m = red[0];
#pragma unroll
    for (int i = 1; i < 8; ++i) m = fmaxf(m, red[i]);

    float e = expf(sc[tid] - m);
    float sv = e;
    for (int o = 16; o; o >>= 1) sv += __shfl_xor_sync(0xffffffffu, sv, o);
    __syncthreads();
    if ((tid & 31) == 0) red[tid >> 5] = sv;
    __syncthreads();
    float tot = 0.0f;
#pragma unroll
    for (int i = 0; i < 8; ++i) tot += red[i];
    __syncthreads();
    sc[tid] = e / tot;
    __syncthreads();

    // weighted sum over time
    for (int dd = tid; dd < 512; dd += 256) {
        float acc = 0.0f;
        for (int t = 0; t < TT; ++t)
            acc += sc[t] * h2[((size_t)t * BBB + b) * 512 + dd];
        outp[(size_t)b * 512 + dd] = acc;
    }
}

// ============================================================================
// Launch
// ============================================================================
extern "C" void kernel_launch(void* const* d_in, const int* in_sizes, int n_in,
                              void* d_out, int out_size)
{
    const float* x        = (const float*)d_in[0];
    const int*   lengths  = (const int*)d_in[1];
    const float* w_ih_l0  = (const float*)d_in[2];
    const float* w_hh_l0  = (const float*)d_in[3];
    const float* b_ih_l0  = (const float*)d_in[4];
    const float* b_hh_l0  = (const float*)d_in[5];
    const float* w_ih_l0r = (const float*)d_in[6];
    const float* w_hh_l0r = (const float*)d_in[7];
    const float* b_ih_l0r = (const float*)d_in[8];
    const float* b_hh_l0r = (const float*)d_in[9];
    const float* w_ih_l1  = (const float*)d_in[10];
    const float* w_hh_l1  = (const float*)d_in[11];
    const float* b_ih_l1  = (const float*)d_in[12];
    const float* b_hh_l1  = (const float*)d_in[13];
    const float* w_ih_l1r = (const float*)d_in[14];
    const float* w_hh_l1r = (const float*)d_in[15];
    const float* b_ih_l1r = (const float*)d_in[16];
    const float* b_hh_l1r = (const float*)d_in[17];
    const float* mlp_w    = (const float*)d_in[18];
    const float* mlp_b    = (const float*)d_in[19];
    const float* ctx      = (const float*)d_in[20];
    float* out = (float*)d_out;

    float *XGF, *XGR, *H1, *H2;
    cudaGetSymbolAddress((void**)&XGF, d_XGF);
    cudaGetSymbolAddress((void**)&XGR, d_XGR);
    cudaGetSymbolAddress((void**)&H1,  d_H1);
    cudaGetSymbolAddress((void**)&H2,  d_H2);

    cudaFuncSetAttribute(lstm_layer,
                         cudaFuncAttributeMaxDynamicSharedMemorySize, LSTM_SMEM);

    dim3 blk(256);
    dim3 g1024(GGG / 128, MROWS / 128);   // (8, 256)
    dim3 g512(512 / 128, MROWS / 128);    // (4, 256)

    // Layer 0: input projections (unreversed x; reversal handled by index map)
    sgemm_bias<0><<<g1024, blk>>>(x, w_ih_l0,  b_ih_l0,  b_hh_l0,  XGF, MROWS, GGG, DD);
    sgemm_bias<0><<<g1024, blk>>>(x, w_ih_l0r, b_ih_l0r, b_hh_l0r, XGR, MROWS, GGG, DD);
    reset_bar_kernel<<<1, 32>>>();
    lstm_layer<<<128, 128, LSTM_SMEM>>>(XGF, XGR, w_hh_l0, w_hh_l0r, lengths, H1);

    // Layer 1
    sgemm_bias<0><<<g1024, blk>>>(H1, w_ih_l1,  b_ih_l1,  b_hh_l1,  XGF, MROWS, GGG, 512);
    sgemm_bias<0><<<g1024, blk>>>(H1, w_ih_l1r, b_ih_l1r, b_hh_l1r, XGR, MROWS, GGG, 512);
    reset_bar_kernel<<<1, 32>>>();
    lstm_layer<<<128, 128, LSTM_SMEM>>>(XGF, XGR, w_hh_l1, w_hh_l1r, lengths, H2);

    // Attention: ann = tanh(H2 . mlp_w^T + mlp_b)  (reuse XGF as scratch)
    sgemm_bias<1><<<g512, blk>>>(H2, mlp_w, mlp_b, (const float*)nullptr,
                                 XGF, MROWS, 512, 512);
    attn_kernel<<<BBB, 256>>>(H2, XGF, ctx, lengths, out);
}

// round 12
// speedup vs baseline: 1.3515x; 1.3515x over previous
#include <cuda_runtime.h>
#include <cuda_bf16.h>
#include <math.h>

// Problem shape (fixed by the bench)
#define TT   256
#define BBB  128
#define HHH  256
#define DD   300
#define GGG  1024              // 4*H
#define MROWS (TT*BBB)         // 32768

// 3-segment split-concat K sizes (Kpad chosen so 3*Kpad % 32 == 0)
#define KP0  320               // D=300 padded to 320
#define K3_0 960               // 3*KP0
#define KP1  512
#define K3_1 1536              // 3*KP1

// ---------------- static device scratch (no runtime allocation) -------------
__device__ float    d_XGF[(size_t)MROWS * GGG];      // gate preacts fwd (reused for ann)
__device__ float    d_XGR[(size_t)MROWS * GGG];      // gate preacts rev
__device__ float    d_H1 [(size_t)MROWS * 512];      // layer-1 output
__device__ float    d_H2 [(size_t)MROWS * 512];      // layer-2 output
__device__ float    d_Hx [16 * 2 * 256 * 16];        // h exchange: [grp][buf][u][b]
__device__ unsigned d_bar[16];                       // group barriers

// bf16 3-segment split operands
__device__ __nv_bfloat16 d_xb [(size_t)MROWS * K3_0];
__device__ __nv_bfloat16 d_h1b[(size_t)MROWS * K3_1];
__device__ __nv_bfloat16 d_h2b[(size_t)MROWS * K3_1];
__device__ __nv_bfloat16 d_w0f[(size_t)1024 * K3_0];
__device__ __nv_bfloat16 d_w0r[(size_t)1024 * K3_0];
__device__ __nv_bfloat16 d_w1f[(size_t)1024 * K3_1];
__device__ __nv_bfloat16 d_w1r[(size_t)1024 * K3_1];
__device__ __nv_bfloat16 d_wm [(size_t)512  * K3_1];

// ============================================================================
// fp32 -> bf16 3-segment split with K padding.
// Activation layout: [ hi | lo | hi ]      Weight layout: [ hi | hi | lo ]
// so  A'.W' = Ah.Wh + Al.Wh + Ah.Wl  (only Al.Wl ~2^-18 dropped).
// ============================================================================
template <int IS_WEIGHT>
__global__ void conv_split3(const float* __restrict__ src, __nv_bfloat16* __restrict__ dst,
                            int M, int K, int Kpad)
{
    int total = M * Kpad;
    for (int idx = blockIdx.x * blockDim.x + threadIdx.x; idx < total;
         idx += gridDim.x * blockDim.x) {
        int m = idx / Kpad, k = idx - m * Kpad;
        float v = (k < K) ? src[(size_t)m * K + k] : 0.0f;
        __nv_bfloat16 hi = __float2bfloat16(v);
        __nv_bfloat16 lo = __float2bfloat16(v - __bfloat162float(hi));
        size_t row = (size_t)m * (3 * Kpad);
        if (IS_WEIGHT) {
            dst[row + k]            = hi;
            dst[row + Kpad + k]     = hi;
            dst[row + 2 * Kpad + k] = lo;
        } else {
            dst[row + k]            = hi;
            dst[row + Kpad + k]     = lo;
            dst[row + 2 * Kpad + k] = hi;
        }
    }
}

// ============================================================================
// bf16 tensor-core GEMM:  C[m][n] = A[m][:] . B[n][:]  (+ epilogue)
//   A: [M, Kp] bf16 row-major, B: [N, Kp] bf16 row-major, C fp32 [M][N]
//   MODE 0: C = acc + b1[n] + b2[n]      MODE 1: C = tanh(acc + b1[n])
// BM=BN=128, BK=32, 256 threads = 8 warps (2 x 4), warp tile 64x32.
// cp.async double-buffered SMEM (80B padded rows -> conflict-free ldmatrix).
// Requires M%128==0, N%128==0, Kp%32==0 (all hold).
// ============================================================================
#define CPASYNC16(s, g) \
    asm volatile("cp.async.cg.shared.global [%0], [%1], 16;" :: "r"(s), "l"(g))
#define LDSMX4(r0, r1, r2, r3, addr) \
    asm volatile("ldmatrix.sync.aligned.m8n8.x4.shared.b16 {%0,%1,%2,%3}, [%4];" \
                 : "=r"(r0), "=r"(r1), "=r"(r2), "=r"(r3) : "r"(addr))
#define MMA16816(d, a, b0, b1) \
    asm volatile("mma.sync.aligned.m16n8k16.row.col.f32.bf16.bf16.f32 " \
                 "{%0,%1,%2,%3}, {%4,%5,%6,%7}, {%8,%9}, {%0,%1,%2,%3};" \
                 : "+f"(d[0]), "+f"(d[1]), "+f"(d[2]), "+f"(d[3]) \
                 : "r"(a[0]), "r"(a[1]), "r"(a[2]), "r"(a[3]), "r"(b0), "r"(b1))

template <int MODE>
__global__ void __launch_bounds__(256)
gemm_bf16(const __nv_bfloat16* __restrict__ A, const __nv_bfloat16* __restrict__ B,
          const float* __restrict__ b1, const float* __restrict__ b2,
          float* __restrict__ C, int N, int Kp)
{
    __shared__ __align__(16) unsigned char smem_raw[2 * 20480]; // [buf][A 10240 | B 10240]
    const unsigned sbase = (unsigned)__cvta_generic_to_shared(smem_raw);

    const int tid  = threadIdx.x;
    const int lane = tid & 31;
    const int wid  = tid >> 5;
    const int warp_m = wid & 1;      // 0..1 (64 rows each)
    const int warp_n = wid >> 1;     // 0..3 (32 cols each)
    const int bm = blockIdx.y, bn = blockIdx.x;
    const int nkt = Kp >> 5;

    // loader: each thread copies two 16B segments of A and two of B per k-tile
    const int s0 = tid, s1 = tid + 256;
    const int r0 = s0 >> 2, c0 = s0 & 3;
    const int r1 = s1 >> 2, c1 = s1 & 3;
    const __nv_bfloat16* gA0 = A + (size_t)(bm * 128 + r0) * Kp + c0 * 8;
    const __nv_bfloat16* gA1 = A + (size_t)(bm * 128 + r1) * Kp + c1 * 8;
    const __nv_bfloat16* gB0 = B + (size_t)(bn * 128 + r0) * Kp + c0 * 8;
    const __nv_bfloat16* gB1 = B + (size_t)(bn * 128 + r1) * Kp + c1 * 8;
    const unsigned oS0 = r0 * 80 + c0 * 16;
    const unsigned oS1 = r1 * 80 + c1 * 16;

    // ldmatrix per-lane addressing: matrices (row-half, k-half) of a 16x16 tile
    const int lrow = ((lane >> 3) & 1) * 8 + (lane & 7);
    const int lseg = lane >> 4;
    const unsigned aoff = (unsigned)((warp_m * 64 + lrow) * 80 + lseg * 16);
    const unsigned boff = (unsigned)((warp_n * 32 + lrow) * 80 + lseg * 16);

    float acc[4][4][4];
#pragma unroll
    for (int i = 0; i < 4; ++i)
#pragma unroll
        for (int j = 0; j < 4; ++j)
#pragma unroll
            for (int c = 0; c < 4; ++c) acc[i][j][c] = 0.0f;

    // prologue: stage k-tile 0
    {
        unsigned sA = sbase, sB = sbase + 10240;
        CPASYNC16(sA + oS0, gA0); CPASYNC16(sA + oS1, gA1);
        CPASYNC16(sB + oS0, gB0); CPASYNC16(sB + oS1, gB1);
        asm volatile("cp.async.commit_group;");
        asm volatile("cp.async.wait_group 0;" ::: "memory");
    }
    __syncthreads();

    for (int kt = 0; kt < nkt; ++kt) {
        const int cur = kt & 1;
        const bool pf = (kt + 1 < nkt);
        if (pf) {
            unsigned sA = sbase + (cur ^ 1) * 20480, sB = sA + 10240;
            int ko = (kt + 1) * 32;
            CPASYNC16(sA + oS0, gA0 + ko); CPASYNC16(sA + oS1, gA1 + ko);
            CPASYNC16(sB + oS0, gB0 + ko); CPASYNC16(sB + oS1, gB1 + ko);
            asm volatile("cp.async.commit_group;");
        }

        const unsigned sA = sbase + cur * 20480 + aoff;
        const unsigned sB = sbase + cur * 20480 + 10240 + boff;
#pragma unroll
        for (int kh = 0; kh < 2; ++kh) {
            unsigned a[4][4], br[2][4];
#pragma unroll
            for (int mi = 0; mi < 4; ++mi)
                LDSMX4(a[mi][0], a[mi][1], a[mi][2], a[mi][3],
                       sA + mi * (16 * 80) + kh * 32);
#pragma unroll
            for (int ng = 0; ng < 2; ++ng)
                LDSMX4(br[ng][0], br[ng][1], br[ng][2], br[ng][3],
                       sB + ng * (16 * 80) + kh * 32);
#pragma unroll
            for (int mi = 0; mi < 4; ++mi) {
#pragma unroll
                for (int ni = 0; ni < 4; ++ni) {
                    const int ng = ni >> 1, w = ni & 1;
                    MMA16816(acc[mi][ni], a[mi], br[ng][w], br[ng][w + 2]);
                }
            }
        }
        if (pf) asm volatile("cp.async.wait_group 0;" ::: "memory");
        __syncthreads();
    }

    // epilogue
    const int g = lane >> 2, tig = lane & 3;
#pragma unroll
    for (int mi = 0; mi < 4; ++mi) {
        const int m0 = bm * 128 + warp_m * 64 + mi * 16 + g;
#pragma unroll
        for (int ni = 0; ni < 4; ++ni) {
            const int n = bn * 128 + warp_n * 32 + ni * 8 + 2 * tig;
            float bb0, bb1;
            if (MODE == 0) { bb0 = b1[n] + b2[n]; bb1 = b1[n + 1] + b2[n + 1]; }
            else           { bb0 = b1[n];         bb1 = b1[n + 1]; }
            float2 v0, v1;
            if (MODE == 0) {
                v0 = make_float2(acc[mi][ni][0] + bb0, acc[mi][ni][1] + bb1);
                v1 = make_float2(acc[mi][ni][2] + bb0, acc[mi][ni][3] + bb1);
            } else {
                v0 = make_float2(tanhf(acc[mi][ni][0] + bb0), tanhf(acc[mi][ni][1] + bb1));
                v1 = make_float2(tanhf(acc[mi][ni][2] + bb0), tanhf(acc[mi][ni][3] + bb1));
            }
            *(float2*)&C[(size_t)m0 * N + n]       = v0;
            *(float2*)&C[(size_t)(m0 + 8) * N + n] = v1;
        }
    }
}

// ============================================================================
// Barrier reset (run before each recurrence launch)
// ============================================================================
__global__ void reset_bar_kernel() {
    if (threadIdx.x < 16) d_bar[threadIdx.x] = 0u;
}

// ============================================================================
// Persistent bidirectional LSTM layer (unchanged; at its FFMA issue floor).
// ============================================================================
#define WS 260
#define LSTM_SMEM ((128 * WS + 16 * WS + 16) * 4)

__global__ void __launch_bounds__(128, 1)
lstm_layer(const float* __restrict__ xgF, const float* __restrict__ xgR,
           const float* __restrict__ whhF, const float* __restrict__ whhR,
           const int* __restrict__ lengths, float* __restrict__ out)
{
    extern __shared__ float sm[];
    float* Wsh  = sm;                    // 128*260
    float* Hs   = sm + 128 * WS;         // 16*260
    int*   lens = (int*)(Hs + 16 * WS);  // 16

    const int tid   = threadIdx.x;
    const int bid   = blockIdx.x;
    const int slice = bid & 7;
    const int chunk = (bid >> 3) & 7;
    const int dir   = bid >> 6;
    const int grp   = dir * 8 + chunk;

    const float* whh = dir ? whhR : whhF;
    const float* xg  = dir ? xgR : xgF;

    if (tid < 16) {
        int l = lengths[chunk * 16 + tid];
        lens[tid] = (l < 1) ? 1 : l;
    }

    for (int i = tid; i < 128 * 64; i += 128) {
        int r  = i >> 6;
        int k4 = i & 63;
        int gg = r >> 5;
        int uu = r & 31;
        float4 v = *(const float4*)&whh[(size_t)(gg * 256 + slice * 32 + uu) * 256 + k4 * 4];
        float* dst = &Wsh[r * WS + k4 * 4];
        dst[0] = v.x; dst[1] = v.y; dst[2] = v.z; dst[3] = v.w;
    }
    __syncthreads();

    const int uu = tid & 31;
    const int bg = (tid >> 5) << 2;
    const float* w0 = Wsh + uu * WS;
    const float* w1 = w0 + 32 * WS;
    const float* w2 = w0 + 64 * WS;
    const float* w3 = w0 + 96 * WS;

    float c[4] = {0.f, 0.f, 0.f, 0.f};

    for (int s = 0; s < TT; ++s) {
        if (s == 0) {
            for (int i = tid; i < 16 * WS; i += 128) Hs[i] = 0.0f;
        } else {
            int buf = s & 1;
            const float* src = d_Hx + ((size_t)(grp * 2 + buf)) * 4096;
            for (int i = tid; i < 4096; i += 128) {
                int u = i >> 4, b = i & 15;
                Hs[b * WS + u] = src[i];
            }
        }
        __syncthreads();

        int t[4];
#pragma unroll
        for (int j = 0; j < 4; ++j) {
            int len = lens[bg + j];
            t[j] = dir ? ((s < len) ? (len - 1 - s) : s) : s;
        }

        float a0[4], a1[4], a2[4], a3[4];
#pragma unroll
        for (int j = 0; j < 4; ++j) {
            size_t row = ((size_t)t[j] * BBB + chunk * 16 + bg + j) * GGG;
            int col = slice * 32 + uu;
            a0[j] = xg[row +   0 + col];
            a1[j] = xg[row + 256 + col];
            a2[j] = xg[row + 512 + col];
            a3[j] = xg[row + 768 + col];
        }

        const float* h0 = Hs + (bg + 0) * WS;
        const float* h1 = Hs + (bg + 1) * WS;
        const float* h2 = Hs + (bg + 2) * WS;
        const float* h3 = Hs + (bg + 3) * WS;

#pragma unroll 4
        for (int k4 = 0; k4 < 64; ++k4) {
            float4 W0 = *(const float4*)(w0 + k4 * 4);
            float4 W1 = *(const float4*)(w1 + k4 * 4);
            float4 W2 = *(const float4*)(w2 + k4 * 4);
            float4 W3 = *(const float4*)(w3 + k4 * 4);
            float4 H0 = *(const float4*)(h0 + k4 * 4);
            float4 H1v = *(const float4*)(h1 + k4 * 4);
            float4 H2v = *(const float4*)(h2 + k4 * 4);
            float4 H3v = *(const float4*)(h3 + k4 * 4);
#define DOT4(acc, Wv, Hv) acc += Wv.x*Hv.x + Wv.y*Hv.y + Wv.z*Hv.z + Wv.w*Hv.w
            DOT4(a0[0], W0, H0); DOT4(a0[1], W0, H1v); DOT4(a0[2], W0, H2v); DOT4(a0[3], W0, H3v);
            DOT4(a1[0], W1, H0); DOT4(a1[1], W1, H1v); DOT4(a1[2], W1, H2v); DOT4(a1[3], W1, H3v);
            DOT4(a2[0], W2, H0); DOT4(a2[1], W2, H1v); DOT4(a2[2], W2, H2v); DOT4(a2[3], W2, H3v);
            DOT4(a3[0], W3, H0); DOT4(a3[1], W3, H1v); DOT4(a3[2], W3, H2v); DOT4(a3[3], W3, H3v);
#undef DOT4
        }

        float hnew[4];
#pragma unroll
        for (int j = 0; j < 4; ++j) {
            float ig = 1.0f / (1.0f + __expf(-a0[j]));
            float fg = 1.0f / (1.0f + __expf(-a1[j]));
            float gg = tanhf(a2[j]);
            float og = 1.0f / (1.0f + __expf(-a3[j]));
            c[j] = fg * c[j] + ig * gg;
            hnew[j] = og * tanhf(c[j]);
        }

        int col = dir * 256 + slice * 32 + uu;
#pragma unroll
        for (int j = 0; j < 4; ++j)
            out[((size_t)t[j] * BBB + chunk * 16 + bg + j) * 512 + col] = hnew[j];

        {
            int buf = (s + 1) & 1;
            float* dst = d_Hx + ((size_t)(grp * 2 + buf)) * 4096
                              + (slice * 32 + uu) * 16 + bg;
            dst[0] = hnew[0]; dst[1] = hnew[1]; dst[2] = hnew[2]; dst[3] = hnew[3];
        }
        __syncthreads();

        if (s < TT - 1) {
            if (tid == 0) {
                __threadfence();
                atomicAdd(&d_bar[grp], 1u);
                unsigned target = 8u * (unsigned)(s + 1);
                unsigned spins = 0;
                while (*((volatile unsigned*)&d_bar[grp]) < target) {
                    if (++spins > (1u << 22)) break;
                }
                __threadfence();
            }
            __syncthreads();
        }
    }
}

// ============================================================================
// Attention: per-batch masked softmax over time + weighted sum (unchanged).
// ============================================================================
__global__ void __launch_bounds__(256)
attn_kernel(const float* __restrict__ h2, const float* __restrict__ ann,
            const float* __restrict__ ctx, const int* __restrict__ lengths,
            float* __restrict__ outp)
{
    __shared__ float ctxs[512];
    __shared__ float sc[256];
    __shared__ float red[8];

    const int b = blockIdx.x;
    const int tid = threadIdx.x;

    for (int i = tid; i < 512; i += 256) ctxs[i] = ctx[i];
    __syncthreads();

    {
        const float* row = ann + ((size_t)tid * BBB + b) * 512;
        float s = 0.0f;
        for (int e = 0; e < 512; e += 4) {
            float4 v = *(const float4*)(row + e);
            s += v.x * ctxs[e] + v.y * ctxs[e + 1] + v.z * ctxs[e + 2] + v.w * ctxs[e + 3];
        }
        int len = lengths[b]; if (len < 1) len = 1;
        sc[tid] = (tid < len) ? s : -1e9f;
    }
    __syncthreads();

    float v = sc[tid];
    for (int o = 16; o; o >>= 1) v = fmaxf(v, __shfl_xor_sync(0xffffffffu, v, o));
    if ((tid & 31) == 0) red[tid >> 5] = v;
    __syncthreads();
    float m = red[0];
#pragma unroll
    for (int i = 1; i < 8; ++i) m = fmaxf(m, red[i]);

    float e = expf(sc[tid] - m);
    float sv = e;
    for (int o = 16; o; o >>= 1) sv += __shfl_xor_sync(0xffffffffu, sv, o);
    __syncthreads();
    if ((tid & 31) == 0) red[tid >> 5] = sv;
    __syncthreads();
    float tot = 0.0f;
#pragma unroll
    for (int i = 0; i < 8; ++i) tot += red[i];
    __syncthreads();
    sc[tid] = e / tot;
    __syncthreads();

    for (int dd = tid; dd < 512; dd += 256) {
        float acc = 0.0f;
        for (int t = 0; t < TT; ++t)
            acc += sc[t] * h2[((size_t)t * BBB + b) * 512 + dd];
        outp[(size_t)b * 512 + dd] = acc;
    }
}

// ============================================================================
// Launch
// ============================================================================
static inline int cdiv(int a, int b) { return (a + b - 1) / b; }

extern "C" void kernel_launch(void* const* d_in, const int* in_sizes, int n_in,
                              void* d_out, int out_size)
{
    const float* x        = (const float*)d_in[0];
    const int*   lengths  = (const int*)d_in[1];
    const float* w_ih_l0  = (const float*)d_in[2];
    const float* w_hh_l0  = (const float*)d_in[3];
    const float* b_ih_l0  = (const float*)d_in[4];
    const float* b_hh_l0  = (const float*)d_in[5];
    const float* w_ih_l0r = (const float*)d_in[6];
    const float* w_hh_l0r = (const float*)d_in[7];
    const float* b_ih_l0r = (const float*)d_in[8];
    const float* b_hh_l0r = (const float*)d_in[9];
    const float* w_ih_l1  = (const float*)d_in[10];
    const float* w_hh_l1  = (const float*)d_in[11];
    const float* b_ih_l1  = (const float*)d_in[12];
    const float* b_hh_l1  = (const float*)d_in[13];
    const float* w_ih_l1r = (const float*)d_in[14];
    const float* w_hh_l1r = (const float*)d_in[15];
    const float* b_ih_l1r = (const float*)d_in[16];
    const float* b_hh_l1r = (const float*)d_in[17];
    const float* mlp_w    = (const float*)d_in[18];
    const float* mlp_b    = (const float*)d_in[19];
    const float* ctx      = (const float*)d_in[20];
    float* out = (float*)d_out;

    float *XGF, *XGR, *H1, *H2;
    __nv_bfloat16 *xb, *h1b, *h2b, *w0f, *w0r, *w1f, *w1r, *wm;
    cudaGetSymbolAddress((void**)&XGF, d_XGF);
    cudaGetSymbolAddress((void**)&XGR, d_XGR);
    cudaGetSymbolAddress((void**)&H1,  d_H1);
    cudaGetSymbolAddress((void**)&H2,  d_H2);
    cudaGetSymbolAddress((void**)&xb,  d_xb);
    cudaGetSymbolAddress((void**)&h1b, d_h1b);
    cudaGetSymbolAddress((void**)&h2b, d_h2b);
    cudaGetSymbolAddress((void**)&w0f, d_w0f);
    cudaGetSymbolAddress((void**)&w0r, d_w0r);
    cudaGetSymbolAddress((void**)&w1f, d_w1f);
    cudaGetSymbolAddress((void**)&w1r, d_w1r);
    cudaGetSymbolAddress((void**)&wm,  d_wm);

    cudaFuncSetAttribute(lstm_layer,
                         cudaFuncAttributeMaxDynamicSharedMemorySize, LSTM_SMEM);

    dim3 blk(256);
    dim3 g1024(GGG / 128, MROWS / 128);   // (8, 256)
    dim3 g512(512 / 128, MROWS / 128);    // (4, 256)

    // --- convert weights + x to split-bf16 (3-segment) ----------------------
    conv_split3<1><<<cdiv(1024 * KP0, 256), 256>>>(w_ih_l0,  w0f, 1024, DD, KP0);
    conv_split3<1><<<cdiv(1024 * KP0, 256), 256>>>(w_ih_l0r, w0r, 1024, DD, KP0);
    conv_split3<1><<<cdiv(1024 * KP1, 256), 256>>>(w_ih_l1,  w1f, 1024, 512, KP1);
    conv_split3<1><<<cdiv(1024 * KP1, 256), 256>>>(w_ih_l1r, w1r, 1024, 512, KP1);
    conv_split3<1><<<cdiv(512  * KP1, 256), 256>>>(mlp_w,    wm,  512,  512, KP1);
    conv_split3<0><<<2048, 256>>>(x, xb, MROWS, DD, KP0);

    // --- layer 0 ------------------------------------------------------------
    gemm_bf16<0><<<g1024, blk>>>(xb, w0f, b_ih_l0,  b_hh_l0,  XGF, GGG, K3_0);
    gemm_bf16<0><<<g1024, blk>>>(xb, w0r, b_ih_l0r, b_hh_l0r, XGR, GGG, K3_0);
    reset_bar_kernel<<<1, 32>>>();
    lstm_layer<<<128, 128, LSTM_SMEM>>>(XGF, XGR, w_hh_l0, w_hh_l0r, lengths, H1);

    // --- layer 1 ------------------------------------------------------------
    conv_split3<0><<<2048, 256>>>(H1, h1b, MROWS, 512, KP1);
    gemm_bf16<0><<<g1024, blk>>>(h1b, w1f, b_ih_l1,  b_hh_l1,  XGF, GGG, K3_1);
    gemm_bf16<0><<<g1024, blk>>>(h1b, w1r, b_ih_l1r, b_hh_l1r, XGR, GGG, K3_1);
    reset_bar_kernel<<<1, 32>>>();
    lstm_layer<<<128, 128, LSTM_SMEM>>>(XGF, XGR, w_hh_l1, w_hh_l1r, lengths, H2);

    // --- attention ----------------------------------------------------------
    conv_split3<0><<<2048, 256>>>(H2, h2b, MROWS, 512, KP1);
    gemm_bf16<1><<<g512, blk>>>(h2b, wm, mlp_b, (const float*)nullptr, XGF, 512, K3_1);
    attn_kernel<<<BBB, 256>>>(H2, XGF, ctx, lengths, out);
}

// round 15
// speedup vs baseline: 1.5913x; 1.1775x over previous
#include <cuda_runtime.h>
#include <cuda_bf16.h>
#include <cuda_fp16.h>
#include <math.h>

// Problem shape (fixed by the bench)
#define TT   256
#define BBB  128
#define HHH  256
#define DD   300
#define GGG  1024              // 4*H
#define MROWS (TT*BBB)         // 32768

// fp16 single-pass K sizes (padded so K % 32 == 0)
#define KP0  320               // D=300 padded to 320
#define KP1  512

// ---------------- static device scratch (no runtime allocation) -------------
__device__ float    d_XGF[(size_t)MROWS * GGG];      // gate preacts fwd (reused for ann)
__device__ float    d_XGR[(size_t)MROWS * GGG];      // gate preacts rev
__device__ float    d_H1 [(size_t)MROWS * 512];      // layer-1 output
__device__ float    d_H2 [(size_t)MROWS * 512];      // layer-2 output
__device__ float    d_Hx [16 * 2 * 256 * 16];        // h exchange: [grp][buf][u][b]
__device__ unsigned d_bar[16];                       // group barriers

// fp16 operands
__device__ __half d_xb [(size_t)MROWS * KP0];
__device__ __half d_h1b[(size_t)MROWS * KP1];
__device__ __half d_h2b[(size_t)MROWS * KP1];
__device__ __half d_w0f[(size_t)1024 * KP0];
__device__ __half d_w0r[(size_t)1024 * KP0];
__device__ __half d_w1f[(size_t)1024 * KP1];
__device__ __half d_w1r[(size_t)1024 * KP1];
__device__ __half d_wm [(size_t)512  * KP1];

// ============================================================================
// fp32 -> fp16 with K padding (zeros beyond K).
// ============================================================================
__global__ void conv_half(const float* __restrict__ src, __half* __restrict__ dst,
                          int M, int K, int Kpad)
{
    int total = M * Kpad;
    for (int idx = blockIdx.x * blockDim.x + threadIdx.x; idx < total;
         idx += gridDim.x * blockDim.x) {
        int m = idx / Kpad, k = idx - m * Kpad;
        float v = (k < K) ? src[(size_t)m * K + k] : 0.0f;
        dst[(size_t)m * Kpad + k] = __float2half(v);
    }
}

// ============================================================================
// fp16 tensor-core GEMM:  C[m][n] = A[m][:] . B[n][:]  (+ epilogue)
//   A: [M, Kp] fp16 row-major, B: [N, Kp] fp16 row-major, C fp32 [M][N]
//   MODE 0: C = acc + b1[n] + b2[n]      MODE 1: C = tanh(acc + b1[n])
// BM=BN=128, BK=32, 256 threads = 8 warps (2 x 4), warp tile 64x32.
// cp.async double-buffered SMEM (80B padded rows -> conflict-free ldmatrix).
// Requires M%128==0, N%128==0, Kp%32==0 (all hold).
// ============================================================================
#define CPASYNC16(s, g) \
    asm volatile("cp.async.cg.shared.global [%0], [%1], 16;" :: "r"(s), "l"(g))
#define LDSMX4(r0, r1, r2, r3, addr) \
    asm volatile("ldmatrix.sync.aligned.m8n8.x4.shared.b16 {%0,%1,%2,%3}, [%4];" \
                 : "=r"(r0), "=r"(r1), "=r"(r2), "=r"(r3) : "r"(addr))
#define MMA16816(d, a, b0, b1) \
    asm volatile("mma.sync.aligned.m16n8k16.row.col.f32.f16.f16.f32 " \
                 "{%0,%1,%2,%3}, {%4,%5,%6,%7}, {%8,%9}, {%0,%1,%2,%3};" \
                 : "+f"(d[0]), "+f"(d[1]), "+f"(d[2]), "+f"(d[3]) \
                 : "r"(a[0]), "r"(a[1]), "r"(a[2]), "r"(a[3]), "r"(b0), "r"(b1))

template <int MODE>
__global__ void __launch_bounds__(256)
gemm_f16(const __half* __restrict__ A, const __half* __restrict__ B,
         const float* __restrict__ b1, const float* __restrict__ b2,
         float* __restrict__ C, int N, int Kp)
{
    __shared__ __align__(16) unsigned char smem_raw[2 * 20480]; // [buf][A 10240 | B 10240]
    const unsigned sbase = (unsigned)__cvta_generic_to_shared(smem_raw);

    const int tid  = threadIdx.x;
    const int lane = tid & 31;
    const int wid  = tid >> 5;
    const int warp_m = wid & 1;      // 0..1 (64 rows each)
    const int warp_n = wid >> 1;     // 0..3 (32 cols each)
    const int bm = blockIdx.y, bn = blockIdx.x;
    const int nkt = Kp >> 5;

    // loader: each thread copies two 16B segments of A and two of B per k-tile
    const int s0 = tid, s1 = tid + 256;
    const int r0 = s0 >> 2, c0 = s0 & 3;
    const int r1 = s1 >> 2, c1 = s1 & 3;
    const __half* gA0 = A + (size_t)(bm * 128 + r0) * Kp + c0 * 8;
    const __half* gA1 = A + (size_t)(bm * 128 + r1) * Kp + c1 * 8;
    const __half* gB0 = B + (size_t)(bn * 128 + r0) * Kp + c0 * 8;
    const __half* gB1 = B + (size_t)(bn * 128 + r1) * Kp + c1 * 8;
    const unsigned oS0 = r0 * 80 + c0 * 16;
    const unsigned oS1 = r1 * 80 + c1 * 16;

    // ldmatrix per-lane addressing: matrices (row-half, k-half) of a 16x16 tile
    const int lrow = ((lane >> 3) & 1) * 8 + (lane & 7);
    const int lseg = lane >> 4;
    const unsigned aoff = (unsigned)((warp_m * 64 + lrow) * 80 + lseg * 16);
    const unsigned boff = (unsigned)((warp_n * 32 + lrow) * 80 + lseg * 16);

    float acc[4][4][4];
#pragma unroll
    for (int i = 0; i < 4; ++i)
#pragma unroll
        for (int j = 0; j < 4; ++j)
#pragma unroll
            for (int c = 0; c < 4; ++c) acc[i][j][c] = 0.0f;

    // prologue: stage k-tile 0
    {
        unsigned sA = sbase, sB = sbase + 10240;
        CPASYNC16(sA + oS0, gA0); CPASYNC16(sA + oS1, gA1);
        CPASYNC16(sB + oS0, gB0); CPASYNC16(sB + oS1, gB1);
        asm volatile("cp.async.commit_group;");
        asm volatile("cp.async.wait_group 0;" ::: "memory");
    }
    __syncthreads();

    for (int kt = 0; kt < nkt; ++kt) {
        const int cur = kt & 1;
        const bool pf = (kt + 1 < nkt);
        if (pf) {
            unsigned sA = sbase + (cur ^ 1) * 20480, sB = sA + 10240;
            int ko = (kt + 1) * 32;
            CPASYNC16(sA + oS0, gA0 + ko); CPASYNC16(sA + oS1, gA1 + ko);
            CPASYNC16(sB + oS0, gB0 + ko); CPASYNC16(sB + oS1, gB1 + ko);
            asm volatile("cp.async.commit_group;");
        }

        const unsigned sA = sbase + cur * 20480 + aoff;
        const unsigned sB = sbase + cur * 20480 + 10240 + boff;
#pragma unroll
        for (int kh = 0; kh < 2; ++kh) {
            unsigned a[4][4], br[2][4];
#pragma unroll
            for (int mi = 0; mi < 4; ++mi)
                LDSMX4(a[mi][0], a[mi][1], a[mi][2], a[mi][3],
                       sA + mi * (16 * 80) + kh * 32);
#pragma unroll
            for (int ng = 0; ng < 2; ++ng)
                LDSMX4(br[ng][0], br[ng][1], br[ng][2], br[ng][3],
                       sB + ng * (16 * 80) + kh * 32);
#pragma unroll
            for (int mi = 0; mi < 4; ++mi) {
#pragma unroll
                for (int ni = 0; ni < 4; ++ni) {
                    const int ng = ni >> 1, w = ni & 1;
                    MMA16816(acc[mi][ni], a[mi], br[ng][w], br[ng][w + 2]);
                }
            }
        }
        if (pf) asm volatile("cp.async.wait_group 0;" ::: "memory");
        __syncthreads();
    }

    // epilogue
    const int g = lane >> 2, tig = lane & 3;
#pragma unroll
    for (int mi = 0; mi < 4; ++mi) {
        const int m0 = bm * 128 + warp_m * 64 + mi * 16 + g;
#pragma unroll
        for (int ni = 0; ni < 4; ++ni) {
            const int n = bn * 128 + warp_n * 32 + ni * 8 + 2 * tig;
            float bb0, bb1;
            if (MODE == 0) { bb0 = b1[n] + b2[n]; bb1 = b1[n + 1] + b2[n + 1]; }
            else           { bb0 = b1[n];         bb1 = b1[n + 1]; }
            float2 v0, v1;
            if (MODE == 0) {
                v0 = make_float2(acc[mi][ni][0] + bb0, acc[mi][ni][1] + bb1);
                v1 = make_float2(acc[mi][ni][2] + bb0, acc[mi][ni][3] + bb1);
            } else {
                v0 = make_float2(tanhf(acc[mi][ni][0] + bb0), tanhf(acc[mi][ni][1] + bb1));
                v1 = make_float2(tanhf(acc[mi][ni][2] + bb0), tanhf(acc[mi][ni][3] + bb1));
            }
            *(float2*)&C[(size_t)m0 * N + n]       = v0;
            *(float2*)&C[(size_t)(m0 + 8) * N + n] = v1;
        }
    }
}

// ============================================================================
// Barrier reset (run before each recurrence launch)
// ============================================================================
__global__ void reset_bar_kernel() {
    if (threadIdx.x < 16) d_bar[threadIdx.x] = 0u;
}

// ============================================================================
// Persistent bidirectional LSTM layer (at its FFMA issue floor).
// ============================================================================
#define WS 260
#define LSTM_SMEM ((128 * WS + 16 * WS + 16) * 4)

__global__ void __launch_bounds__(128, 1)
lstm_layer(const float* __restrict__ xgF, const float* __restrict__ xgR,
           const float* __restrict__ whhF, const float* __restrict__ whhR,
           const int* __restrict__ lengths, float* __restrict__ out)
{
    extern __shared__ float sm[];
    float* Wsh  = sm;                    // 128*260
    float* Hs   = sm + 128 * WS;         // 16*260
    int*   lens = (int*)(Hs + 16 * WS);  // 16

    const int tid   = threadIdx.x;
    const int bid   = blockIdx.x;
    const int slice = bid & 7;
    const int chunk = (bid >> 3) & 7;
    const int dir   = bid >> 6;
    const int grp   = dir * 8 + chunk;

    const float* whh = dir ? whhR : whhF;
    const float* xg  = dir ? xgR : xgF;

    if (tid < 16) {
        int l = lengths[chunk * 16 + tid];
        lens[tid] = (l < 1) ? 1 : l;
    }

    for (int i = tid; i < 128 * 64; i += 128) {
        int r  = i >> 6;
        int k4 = i & 63;
        int gg = r >> 5;
        int uu = r & 31;
        float4 v = *(const float4*)&whh[(size_t)(gg * 256 + slice * 32 + uu) * 256 + k4 * 4];
        float* dst = &Wsh[r * WS + k4 * 4];
        dst[0] = v.x; dst[1] = v.y; dst[2] = v.z; dst[3] = v.w;
    }
    __syncthreads();

    const int uu = tid & 31;
    const int bg = (tid >> 5) << 2;
    const float* w0 = Wsh + uu * WS;
    const float* w1 = w0 + 32 * WS;
    const float* w2 = w0 + 64 * WS;
    const float* w3 = w0 + 96 * WS;

    float c[4] = {0.f, 0.f, 0.f, 0.f};

    for (int s = 0; s < TT; ++s) {
        if (s == 0) {
            for (int i = tid; i < 16 * WS; i += 128) Hs[i] = 0.0f;
        } else {
            int buf = s & 1;
            const float* src = d_Hx + ((size_t)(grp * 2 + buf)) * 4096;
            for (int i = tid; i < 4096; i += 128) {
                int u = i >> 4, b = i & 15;
                Hs[b * WS + u] = src[i];
            }
        }
        __syncthreads();

        int t[4];
#pragma unroll
        for (int j = 0; j < 4; ++j) {
            int len = lens[bg + j];
            t[j] = dir ? ((s < len) ? (len - 1 - s) : s) : s;
        }

        float a0[4], a1[4], a2[4], a3[4];
#pragma unroll
        for (int j = 0; j < 4; ++j) {
            size_t row = ((size_t)t[j] * BBB + chunk * 16 + bg + j) * GGG;
            int col = slice * 32 + uu;
            a0[j] = xg[row +   0 + col];
            a1[j] = xg[row + 256 + col];
            a2[j] = xg[row + 512 + col];
            a3[j] = xg[row + 768 + col];
        }

        const float* h0 = Hs + (bg + 0) * WS;
        const float* h1 = Hs + (bg + 1) * WS;
        const float* h2 = Hs + (bg + 2) * WS;
        const float* h3 = Hs + (bg + 3) * WS;

#pragma unroll 4
        for (int k4 = 0; k4 < 64; ++k4) {
            float4 W0 = *(const float4*)(w0 + k4 * 4);
            float4 W1 = *(const float4*)(w1 + k4 * 4);
            float4 W2 = *(const float4*)(w2 + k4 * 4);
            float4 W3 = *(const float4*)(w3 + k4 * 4);
            float4 H0 = *(const float4*)(h0 + k4 * 4);
            float4 H1v = *(const float4*)(h1 + k4 * 4);
            float4 H2v = *(const float4*)(h2 + k4 * 4);
            float4 H3v = *(const float4*)(h3 + k4 * 4);
#define DOT4(acc, Wv, Hv) acc += Wv.x*Hv.x + Wv.y*Hv.y + Wv.z*Hv.z + Wv.w*Hv.w
            DOT4(a0[0], W0, H0); DOT4(a0[1], W0, H1v); DOT4(a0[2], W0, H2v); DOT4(a0[3], W0, H3v);
            DOT4(a1[0], W1, H0); DOT4(a1[1], W1, H1v); DOT4(a1[2], W1, H2v); DOT4(a1[3], W1, H3v);
            DOT4(a2[0], W2, H0); DOT4(a2[1], W2, H1v); DOT4(a2[2], W2, H2v); DOT4(a2[3], W2, H3v);
            DOT4(a3[0], W3, H0); DOT4(a3[1], W3, H1v); DOT4(a3[2], W3, H2v); DOT4(a3[3], W3, H3v);
#undef DOT4
        }

        float hnew[4];
#pragma unroll
        for (int j = 0; j < 4; ++j) {
            float ig = 1.0f / (1.0f + __expf(-a0[j]));
            float fg = 1.0f / (1.0f + __expf(-a1[j]));
            float gg = tanhf(a2[j]);
            float og = 1.0f / (1.0f + __expf(-a3[j]));
            c[j] = fg * c[j] + ig * gg;
            hnew[j] = og * tanhf(c[j]);
        }

        int col = dir * 256 + slice * 32 + uu;
#pragma unroll
        for (int j = 0; j < 4; ++j)
            out[((size_t)t[j] * BBB + chunk * 16 + bg + j) * 512 + col] = hnew[j];

        {
            int buf = (s + 1) & 1;
            float* dst = d_Hx + ((size_t)(grp * 2 + buf)) * 4096
                              + (slice * 32 + uu) * 16 + bg;
            dst[0] = hnew[0]; dst[1] = hnew[1]; dst[2] = hnew[2]; dst[3] = hnew[3];
        }
        __syncthreads();

        if (s < TT - 1) {
            if (tid == 0) {
                __threadfence();
                atomicAdd(&d_bar[grp], 1u);
                unsigned target = 8u * (unsigned)(s + 1);
                unsigned spins = 0;
                while (*((volatile unsigned*)&d_bar[grp]) < target) {
                    if (++spins > (1u << 22)) break;
                }
                __threadfence();
            }
            __syncthreads();
        }
    }
}

// ============================================================================
// Attention: per-batch masked softmax over time + weighted sum.
// ============================================================================
__global__ void __launch_bounds__(256)
attn_kernel(const float* __restrict__ h2, const float* __restrict__ ann,
            const float* __restrict__ ctx, const int* __restrict__ lengths,
            float* __restrict__ outp)
{
    __shared__ float ctxs[512];
    __shared__ float sc[256];
    __shared__ float red[8];

    const int b = blockIdx.x;
    const int tid = threadIdx.x;

    for (int i = tid; i < 512; i += 256) ctxs[i] = ctx[i];
    __syncthreads();

    {
        const float* row = ann + ((size_t)tid * BBB + b) * 512;
        float s = 0.0f;
        for (int e = 0; e < 512; e += 4) {
            float4 v = *(const float4*)(row + e);
            s += v.x * ctxs[e] + v.y * ctxs[e + 1] + v.z * ctxs[e + 2] + v.w * ctxs[e + 3];
        }
        int len = lengths[b]; if (len < 1) len = 1;
        sc[tid] = (tid < len) ? s : -1e9f;
    }
    __syncthreads();

    float v = sc[tid];
    for (int o = 16; o; o >>= 1) v = fmaxf(v, __shfl_xor_sync(0xffffffffu, v, o));
    if ((tid & 31) == 0) red[tid >> 5] = v;
    __syncthreads();
    float m = red[0];
#pragma unroll
    for (int i = 1; i < 8; ++i) m = fmaxf(m, red[i]);

    float e = expf(sc[tid] - m);
    float sv = e;
    for (int o = 16; o; o >>= 1) sv += __shfl_xor_sync(0xffffffffu, sv, o);
    __syncthreads();
    if ((tid & 31) == 0) red[tid >> 5] = sv;
    __syncthreads();
    float tot = 0.0f;
#pragma unroll
    for (int i = 0; i < 8; ++i) tot += red[i];
    __syncthreads();
    sc[tid] = e / tot;
    __syncthreads();

    for (int dd = tid; dd < 512; dd += 256) {
        float acc = 0.0f;
        for (int t = 0; t < TT; ++t)
            acc += sc[t] * h2[((size_t)t * BBB + b) * 512 + dd];
        outp[(size_t)b * 512 + dd] = acc;
    }
}

// ============================================================================
// Launch
// ============================================================================
static inline int cdiv(int a, int b) { return (a + b - 1) / b; }

extern "C" void kernel_launch(void* const* d_in, const int* in_sizes, int n_in,
                              void* d_out, int out_size)
{
    const float* x        = (const float*)d_in[0];
    const int*   lengths  = (const int*)d_in[1];
    const float* w_ih_l0  = (const float*)d_in[2];
    const float* w_hh_l0  = (const float*)d_in[3];
    const float* b_ih_l0  = (const float*)d_in[4];
    const float* b_hh_l0  = (const float*)d_in[5];
    const float* w_ih_l0r = (const float*)d_in[6];
    const float* w_hh_l0r = (const float*)d_in[7];
    const float* b_ih_l0r = (const float*)d_in[8];
    const float* b_hh_l0r = (const float*)d_in[9];
    const float* w_ih_l1  = (const float*)d_in[10];
    const float* w_hh_l1  = (const float*)d_in[11];
    const float* b_ih_l1  = (const float*)d_in[12];
    const float* b_hh_l1  = (const float*)d_in[13];
    const float* w_ih_l1r = (const float*)d_in[14];
    const float* w_hh_l1r = (const float*)d_in[15];
    const float* b_ih_l1r = (const float*)d_in[16];
    const float* b_hh_l1r = (const float*)d_in[17];
    const float* mlp_w    = (const float*)d_in[18];
    const float* mlp_b    = (const float*)d_in[19];
    const float* ctx      = (const float*)d_in[20];
    float* out = (float*)d_out;

    float *XGF, *XGR, *H1, *H2;
    __half *xb, *h1b, *h2b, *w0f, *w0r, *w1f, *w1r, *wm;
    cudaGetSymbolAddress((void**)&XGF, d_XGF);
    cudaGetSymbolAddress((void**)&XGR, d_XGR);
    cudaGetSymbolAddress((void**)&H1,  d_H1);
    cudaGetSymbolAddress((void**)&H2,  d_H2);
    cudaGetSymbolAddress((void**)&xb,  d_xb);
    cudaGetSymbolAddress((void**)&h1b, d_h1b);
    cudaGetSymbolAddress((void**)&h2b, d_h2b);
    cudaGetSymbolAddress((void**)&w0f, d_w0f);
    cudaGetSymbolAddress((void**)&w0r, d_w0r);
    cudaGetSymbolAddress((void**)&w1f, d_w1f);
    cudaGetSymbolAddress((void**)&w1r, d_w1r);
    cudaGetSymbolAddress((void**)&wm,  d_wm);

    cudaFuncSetAttribute(lstm_layer,
                         cudaFuncAttributeMaxDynamicSharedMemorySize, LSTM_SMEM);

    dim3 blk(256);
    dim3 g1024(GGG / 128, MROWS / 128);   // (8, 256)
    dim3 g512(512 / 128, MROWS / 128);    // (4, 256)

    // --- convert weights + x to fp16 ----------------------------------------
    conv_half<<<cdiv(1024 * KP0, 256), 256>>>(w_ih_l0,  w0f, 1024, DD, KP0);
    conv_half<<<cdiv(1024 * KP0, 256), 256>>>(w_ih_l0r, w0r, 1024, DD, KP0);
    conv_half<<<cdiv(1024 * KP1, 256), 256>>>(w_ih_l1,  w1f, 1024, 512, KP1);
    conv_half<<<cdiv(1024 * KP1, 256), 256>>>(w_ih_l1r, w1r, 1024, 512, KP1);
    conv_half<<<cdiv(512  * KP1, 256), 256>>>(mlp_w,    wm,  512,  512, KP1);
    conv_half<<<2048, 256>>>(x, xb, MROWS, DD, KP0);

    // --- layer 0 ------------------------------------------------------------
    gemm_f16<0><<<g1024, blk>>>(xb, w0f, b_ih_l0,  b_hh_l0,  XGF, GGG, KP0);
    gemm_f16<0><<<g1024, blk>>>(xb, w0r, b_ih_l0r, b_hh_l0r, XGR, GGG, KP0);
    reset_bar_kernel<<<1, 32>>>();
    lstm_layer<<<128, 128, LSTM_SMEM>>>(XGF, XGR, w_hh_l0, w_hh_l0r, lengths, H1);

    // --- layer 1 ------------------------------------------------------------
    conv_half<<<2048, 256>>>(H1, h1b, MROWS, 512, KP1);
    gemm_f16<0><<<g1024, blk>>>(h1b, w1f, b_ih_l1,  b_hh_l1,  XGF, GGG, KP1);
    gemm_f16<0><<<g1024, blk>>>(h1b, w1r, b_ih_l1r, b_hh_l1r, XGR, GGG, KP1);
    reset_bar_kernel<<<1, 32>>>();
    lstm_layer<<<128, 128, LSTM_SMEM>>>(XGF, XGR, w_hh_l1, w_hh_l1r, lengths, H2);

    // --- attention ----------------------------------------------------------
    conv_half<<<2048, 256>>>(H2, h2b, MROWS, 512, KP1);
    gemm_f16<1><<<g512, blk>>>(h2b, wm, mlp_b, (const float*)nullptr, XGF, 512, KP1);
    attn_kernel<<<BBB, 256>>>(H2, XGF, ctx, lengths, out);
}